// round 5
// baseline (speedup 1.0000x reference)
#include <cuda_runtime.h>
#include <math.h>

#define MAX_N   1024
#define EPS     1e-4f
#define CHUNKS  8
#define LISTCAP 131072

// ---- scratch (__device__ globals; no allocation allowed) ----
__device__ float g_diag[MAX_N * 64];    // per-node sum of R^T R
__device__ float g_dis [MAX_N * 64];    // per-node D^{-1/2}
__device__ int   g_cnt [CHUNKS];        // per-band work counts
__device__ int   g_list[LISTCAP];       // per-band compact block-id lists

// ---- bucket every output block (edge p -> id=p, diag v -> id=P+v) by i-band ----
__global__ void k_bucket(const int* __restrict__ E, int P, int n, int rpc, int cap) {
    int t = blockIdx.x * blockDim.x + threadIdx.x;
    if (t >= P + n) return;
    int i = (t < P) ? E[2 * t] : (t - P);
    int band = i / rpc;
    int idx = atomicAdd(&g_cnt[band], 1);
    g_list[band * cap + idx] = t;
}

// ---- per-edge FtF = R^T R, atomically accumulated into g_diag[i] ----
__global__ void k_ftf(const float* __restrict__ R, const int* __restrict__ E, int P) {
    int gid = blockIdx.x * blockDim.x + threadIdx.x;
    if (gid >= P * 64) return;
    int p = gid >> 6;
    int e = gid & 63;
    int r = e >> 3, c = e & 7;
    int i = E[2 * p];
    const float* Rp = R + (size_t)p * 64;
    float v = 0.f;
#pragma unroll
    for (int k = 0; k < 8; k++) v += Rp[k * 8 + r] * Rp[k * 8 + c];
    atomicAdd(&g_diag[i * 64 + e], v);
}

// ---- per-node D^{-1/2} via coupled Newton-Schulz (SPD, lambda >= EPS) ----
__global__ void k_ns(int n) {
    __shared__ float Y[64], Z[64], G[64], red[64];
    int v = blockIdx.x;
    int t = threadIdx.x;
    int r = t >> 3, c = t & 7;

    float a = g_diag[v * 64 + r * 8 + c];
    float b = g_diag[v * 64 + c * 8 + r];
    float d = 0.5f * (a + b) + ((r == c) ? EPS : 0.f);

    red[t] = d * d;
    __syncthreads();
    if (t < 32) red[t] += red[t + 32];
    __syncthreads();
    if (t < 32) {
        float s = red[t];
#pragma unroll
        for (int o = 16; o > 0; o >>= 1) s += __shfl_down_sync(0xffffffffu, s, o);
        if (t == 0) red[0] = s;
    }
    __syncthreads();
    float s = sqrtf(red[0]);
    float inv_s = 1.f / s;

    Y[t] = d * inv_s;
    Z[t] = (r == c) ? 1.f : 0.f;
    __syncthreads();

    for (int it = 0; it < 24; it++) {
        float acc = 0.f;
#pragma unroll
        for (int k = 0; k < 8; k++) acc += Z[r * 8 + k] * Y[k * 8 + c];
        float g = ((r == c) ? 1.5f : 0.f) - 0.5f * acc;
        __syncthreads();
        G[t] = g;
        __syncthreads();
        float ny = 0.f, nz = 0.f;
#pragma unroll
        for (int k = 0; k < 8; k++) {
            ny += Y[r * 8 + k] * G[k * 8 + c];
            nz += G[r * 8 + k] * Z[k * 8 + c];
        }
        __syncthreads();
        Y[t] = ny;
        Z[t] = nz;
        __syncthreads();
    }

    g_dis[v * 64 + t] = Z[t] * rsqrtf(s);
}

// ---- one 64-thread block per listed nonzero 8x8 output block (one band) ----
//      reverse edge of p is (p + P/2) % P by construction (directed = [fwd; bwd])
__global__ void k_blocks(const float* __restrict__ R, const int* __restrict__ E,
                         const float* __restrict__ L1, float* __restrict__ out,
                         int P, int n, int band, int cap) {
    __shared__ float M1[64], M2[64], Di[64], Dj[64], B[64], T[64];
    if ((int)blockIdx.x >= g_cnt[band]) return;
    int b = g_list[band * cap + blockIdx.x];
    int t = threadIdx.x;          // 0..63
    bool is_edge = (b < P);
    int i, j;
    if (is_edge) {
        int2 e = ((const int2*)E)[b];
        i = e.x; j = e.y;
    } else {
        i = j = b - P;
    }

    int r = t >> 3, c = t & 7;
    int g = t & 15, sel = t >> 4;     // cooperative float4 loads
    float sgn = 0.f;

    if (is_edge) {
        int half = P >> 1;
        int rev = (b < half) ? (b + half) : (b - half);
        float l = L1[(size_t)i * n + j];
        sgn = (l > 0.f) ? 1.f : ((l < 0.f) ? -1.f : 0.f);
        if (sel == 0) {
            ((float4*)M1)[g] = ((const float4*)(R + (size_t)rev * 64))[g];  // R_ji
        } else if (sel == 1) {
            ((float4*)M2)[g] = ((const float4*)(R + (size_t)b * 64))[g];    // R_ij
        } else if (sel == 2) {
            ((float4*)Di)[g] = ((const float4*)(g_dis + (size_t)i * 64))[g];
        } else {
            ((float4*)Dj)[g] = ((const float4*)(g_dis + (size_t)j * 64))[g];
        }
    } else {
        if (sel == 0) {
            ((float4*)B)[g]  = ((const float4*)(g_diag + (size_t)i * 64))[g];
        } else if (sel == 2) {
            ((float4*)Di)[g] = ((const float4*)(g_dis + (size_t)i * 64))[g];
        } else if (sel == 3) {
            ((float4*)Dj)[g] = ((const float4*)(g_dis + (size_t)i * 64))[g];
        }
    }
    __syncthreads();

    if (is_edge) {
        float s = 0.f;
#pragma unroll
        for (int k = 0; k < 8; k++) s += M1[k * 8 + r] * M2[k * 8 + c];
        B[t] = -sgn * s;
    }
    __syncthreads();
    {
        float s = 0.f;
#pragma unroll
        for (int k = 0; k < 8; k++) s += Di[r * 8 + k] * B[k * 8 + c];
        T[t] = s;
    }
    __syncthreads();
    {
        float s = 0.f;
#pragma unroll
        for (int k = 0; k < 8; k++) s += T[r * 8 + k] * Dj[k * 8 + c];
        size_t nd = (size_t)n * 8;
        out[((size_t)i * 8 + r) * nd + (size_t)j * 8 + c] = s;
    }
}

extern "C" void kernel_launch(void* const* d_in, const int* in_sizes, int n_in,
                              void* d_out, int out_size) {
    const float* R  = (const float*)d_in[0];  // (P, 8, 8)
    const int*   E  = (const int*)  d_in[1];  // (P, 2)
    const float* L1 = (const float*)d_in[3];  // (n, n)

    int P = in_sizes[1] / 2;
    int n = (int)(sqrt((double)in_sizes[3]) + 0.5);

    // one-time host-side resources (streams/events are NOT device memory)
    static bool inited = false;
    static cudaStream_t side;
    static cudaEvent_t ev_fork;
    static cudaEvent_t ev_band[CHUNKS];
    static void* diag_ptr;
    static void* cnt_ptr;
    if (!inited) {
        cudaStreamCreateWithFlags(&side, cudaStreamNonBlocking);
        cudaEventCreateWithFlags(&ev_fork, cudaEventDisableTiming);
        for (int c = 0; c < CHUNKS; c++)
            cudaEventCreateWithFlags(&ev_band[c], cudaEventDisableTiming);
        cudaGetSymbolAddress(&diag_ptr, g_diag);
        cudaGetSymbolAddress(&cnt_ptr, g_cnt);
        inited = true;
    }

    int rpc = (n + CHUNKS - 1) / CHUNKS;                 // node rows per band
    int cap = 2 * ((P + n) / CHUNKS + 64);               // per-band list capacity
    if (cap * CHUNKS > LISTCAP) cap = LISTCAP / CHUNKS;  // safety clamp

    size_t total_bytes = (size_t)out_size * sizeof(float);
    size_t band_bytes = (size_t)rpc * 8 * (size_t)n * 8 * sizeof(float);

    // side stream: zero the whole output in CHUNKS bands, starting at t=0
    cudaEventRecord(ev_fork, 0);
    cudaStreamWaitEvent(side, ev_fork, 0);
    for (int c = 0; c < CHUNKS; c++) {
        size_t off = (size_t)c * band_bytes;
        if (off < total_bytes) {
            size_t len = band_bytes;
            if (off + len > total_bytes) len = total_bytes - off;
            cudaMemsetAsync((char*)d_out + off, 0, len, side);
        }
        cudaEventRecord(ev_band[c], side);
    }

    // main stream: prefix chain (hidden under the first memset bands)
    cudaMemsetAsync(diag_ptr, 0, (size_t)n * 64 * sizeof(float), 0);
    cudaMemsetAsync(cnt_ptr, 0, CHUNKS * sizeof(int), 0);
    k_bucket<<<(P + n + 255) / 256, 256>>>(E, P, n, rpc, cap);
    k_ftf<<<(P * 64 + 255) / 256, 256>>>(R, E, P);
    k_ns<<<n, 64>>>(n);

    // pipelined block writer, all on main stream; band c gated by its memset
    int grid = cap;  // fixed upper bound; blocks beyond g_cnt[band] exit fast
    for (int c = 0; c < CHUNKS; c++) {
        if (c * rpc >= n) break;
        cudaStreamWaitEvent(0, ev_band[c], 0);
        k_blocks<<<grid, 64>>>(R, E, L1, (float*)d_out, P, n, c, cap);
    }
}

// round 7
// speedup vs baseline: 1.7686x; 1.7686x over previous
#include <cuda_runtime.h>
#include <math.h>

#define MAX_N 1024
#define EPS   1e-4f

// ---- scratch (__device__ globals; no allocation allowed) ----
__device__ float    g_diag  [MAX_N * 64];           // per-node sum of R^T R
__device__ float    g_dis   [MAX_N * 64];           // per-node D^{-1/2}
__device__ unsigned g_bitmap[MAX_N * MAX_N / 32];   // 128KB: bit(i,j)=1 -> block written by k_blocks

// ---- build nonzero-block bitmap: edges + diagonal ----
__global__ void k_bitmap(const int* __restrict__ E, int P, int n) {
    int t = blockIdx.x * blockDim.x + threadIdx.x;
    if (t >= P + n) return;
    int i, j;
    if (t < P) { int2 e = ((const int2*)E)[t]; i = e.x; j = e.y; }
    else       { i = j = t - P; }
    atomicOr(&g_bitmap[(i * n + j) >> 5], 1u << (j & 31));
}

// ---- zero every output float4 whose 8x8 block is NOT in the bitmap.
//      grid = (ceil(2n/256) chunks, 8n rows); one predicated streaming store/thread ----
__global__ void k_zero(float4* __restrict__ out, int n) {
    int orow = blockIdx.y;                              // 0 .. 8n-1
    int f4   = blockIdx.x * blockDim.x + threadIdx.x;   // float4 index within row
    int row_f4 = 2 * n;
    if (f4 >= row_f4) return;
    int i = orow >> 3;
    int j = f4 >> 1;
    unsigned w = g_bitmap[(i * n + j) >> 5];
    if (!(w & (1u << (j & 31)))) {
        const float4 z = make_float4(0.f, 0.f, 0.f, 0.f);
        __stcs(&out[(size_t)orow * row_f4 + f4], z);    // streaming: don't pollute L2
    }
}

// ---- per-edge FtF = R^T R, atomically accumulated into g_diag[i] ----
__global__ void k_ftf(const float* __restrict__ R, const int* __restrict__ E, int P) {
    int gid = blockIdx.x * blockDim.x + threadIdx.x;
    if (gid >= P * 64) return;
    int p = gid >> 6;
    int e = gid & 63;
    int r = e >> 3, c = e & 7;
    int i = E[2 * p];
    const float* Rp = R + (size_t)p * 64;
    float v = 0.f;
#pragma unroll
    for (int k = 0; k < 8; k++) v += Rp[k * 8 + r] * Rp[k * 8 + c];
    atomicAdd(&g_diag[i * 64 + e], v);
}

// ---- per-node D^{-1/2} via coupled Newton-Schulz (SPD, lambda >= EPS) ----
__global__ void k_ns(int n) {
    __shared__ float Y[64], Z[64], G[64], red[64];
    int v = blockIdx.x;
    int t = threadIdx.x;
    int r = t >> 3, c = t & 7;

    float a = g_diag[v * 64 + r * 8 + c];
    float b = g_diag[v * 64 + c * 8 + r];
    float d = 0.5f * (a + b) + ((r == c) ? EPS : 0.f);

    red[t] = d * d;
    __syncthreads();
    if (t < 32) red[t] += red[t + 32];
    __syncthreads();
    if (t < 32) {
        float s = red[t];
#pragma unroll
        for (int o = 16; o > 0; o >>= 1) s += __shfl_down_sync(0xffffffffu, s, o);
        if (t == 0) red[0] = s;
    }
    __syncthreads();
    float s = sqrtf(red[0]);
    float inv_s = 1.f / s;

    Y[t] = d * inv_s;
    Z[t] = (r == c) ? 1.f : 0.f;
    __syncthreads();

    for (int it = 0; it < 24; it++) {
        float acc = 0.f;
#pragma unroll
        for (int k = 0; k < 8; k++) acc += Z[r * 8 + k] * Y[k * 8 + c];
        float g = ((r == c) ? 1.5f : 0.f) - 0.5f * acc;
        __syncthreads();
        G[t] = g;
        __syncthreads();
        float ny = 0.f, nz = 0.f;
#pragma unroll
        for (int k = 0; k < 8; k++) {
            ny += Y[r * 8 + k] * G[k * 8 + c];
            nz += G[r * 8 + k] * Z[k * 8 + c];
        }
        __syncthreads();
        Y[t] = ny;
        Z[t] = nz;
        __syncthreads();
    }

    g_dis[v * 64 + t] = Z[t] * rsqrtf(s);
}

// ---- one 64-thread block per nonzero 8x8 output block.
//      reverse edge of p is (p + P/2) % P by construction (directed = [fwd; bwd]) ----
__global__ void k_blocks(const float* __restrict__ R, const int* __restrict__ E,
                         const float* __restrict__ L1, float* __restrict__ out,
                         int P, int n) {
    __shared__ float M1[64], M2[64], Di[64], Dj[64], B[64], T[64];
    int b = blockIdx.x;
    int t = threadIdx.x;          // 0..63
    bool is_edge = (b < P);
    int i, j;
    if (is_edge) {
        int2 e = ((const int2*)E)[b];
        i = e.x; j = e.y;
    } else {
        i = j = b - P;
    }

    int r = t >> 3, c = t & 7;
    int g = t & 15, sel = t >> 4;     // cooperative float4 loads
    float sgn = 0.f;

    if (is_edge) {
        int half = P >> 1;
        int rev = (b < half) ? (b + half) : (b - half);
        float l = L1[(size_t)i * n + j];
        sgn = (l > 0.f) ? 1.f : ((l < 0.f) ? -1.f : 0.f);
        if (sel == 0) {
            ((float4*)M1)[g] = ((const float4*)(R + (size_t)rev * 64))[g];  // R_ji
        } else if (sel == 1) {
            ((float4*)M2)[g] = ((const float4*)(R + (size_t)b * 64))[g];    // R_ij
        } else if (sel == 2) {
            ((float4*)Di)[g] = ((const float4*)(g_dis + (size_t)i * 64))[g];
        } else {
            ((float4*)Dj)[g] = ((const float4*)(g_dis + (size_t)j * 64))[g];
        }
    } else {
        if (sel == 0) {
            ((float4*)B)[g]  = ((const float4*)(g_diag + (size_t)i * 64))[g];
        } else if (sel == 2) {
            ((float4*)Di)[g] = ((const float4*)(g_dis + (size_t)i * 64))[g];
        } else if (sel == 3) {
            ((float4*)Dj)[g] = ((const float4*)(g_dis + (size_t)i * 64))[g];
        }
    }
    __syncthreads();

    if (is_edge) {
        float s = 0.f;
#pragma unroll
        for (int k = 0; k < 8; k++) s += M1[k * 8 + r] * M2[k * 8 + c];
        B[t] = -sgn * s;
    }
    __syncthreads();
    {
        float s = 0.f;
#pragma unroll
        for (int k = 0; k < 8; k++) s += Di[r * 8 + k] * B[k * 8 + c];
        T[t] = s;
    }
    __syncthreads();
    {
        float s = 0.f;
#pragma unroll
        for (int k = 0; k < 8; k++) s += T[r * 8 + k] * Dj[k * 8 + c];
        size_t nd = (size_t)n * 8;
        out[((size_t)i * 8 + r) * nd + (size_t)j * 8 + c] = s;
    }
}

extern "C" void kernel_launch(void* const* d_in, const int* in_sizes, int n_in,
                              void* d_out, int out_size) {
    const float* R  = (const float*)d_in[0];  // (P, 8, 8)
    const int*   E  = (const int*)  d_in[1];  // (P, 2)
    const float* L1 = (const float*)d_in[3];  // (n, n)

    int P = in_sizes[1] / 2;
    int n = (int)(sqrt((double)in_sizes[3]) + 0.5);

    // one-time host-side resources (streams/events are NOT device memory)
    static bool inited = false;
    static cudaStream_t side;
    static cudaEvent_t ev_bitmap, ev_join;
    static void* diag_ptr;
    static void* bm_ptr;
    if (!inited) {
        cudaStreamCreateWithFlags(&side, cudaStreamNonBlocking);
        cudaEventCreateWithFlags(&ev_bitmap, cudaEventDisableTiming);
        cudaEventCreateWithFlags(&ev_join, cudaEventDisableTiming);
        cudaGetSymbolAddress(&diag_ptr, g_diag);
        cudaGetSymbolAddress(&bm_ptr, g_bitmap);
        inited = true;
    }

    // main stream: reset scratch, build bitmap (tiny prefix)
    cudaMemsetAsync(diag_ptr, 0, (size_t)n * 64 * sizeof(float), 0);
    cudaMemsetAsync(bm_ptr, 0, (size_t)n * n / 8, 0);
    k_bitmap<<<(P + n + 255) / 256, 256>>>(E, P, n);
    cudaEventRecord(ev_bitmap, 0);

    // side stream: streaming zero of all zero-blocks (bulk of the time)
    cudaStreamWaitEvent(side, ev_bitmap, 0);
    {
        dim3 grid((2 * n + 255) / 256, 8 * n);   // (f4 chunks per row, output rows)
        k_zero<<<grid, 256, 0, side>>>((float4*)d_out, n);
    }
    cudaEventRecord(ev_join, side);

    // main stream: compute chain + nonzero-block writer (runs under k_zero)
    k_ftf<<<(P * 64 + 255) / 256, 256>>>(R, E, P);
    k_ns<<<n, 64>>>(n);
    k_blocks<<<P + n, 64>>>(R, E, L1, (float*)d_out, P, n);

    // join: side stream's zero writes complete before launch is done
    cudaStreamWaitEvent(0, ev_join, 0);
}